// round 8
// baseline (speedup 1.0000x reference)
#include <cuda_runtime.h>
#include <cuda_bf16.h>
#include <cstdint>
#include <math.h>

// ---------------- problem constants ----------------
#define BATCH   32
#define SEQ     1024
#define CH      384
#define MAXOUT  3072
#define ROWS    (BATCH*SEQ)   // 32768
#define NPAIRS  (ROWS/2)      // 16384 output pairs (Winograd F(2,3))
#define PPB     512           // pairs per batch

// Winograd GEMM tiling: per CTA 32 pairs x 4 domains = 128 M-rows, N=384, K=C=384
#define NP      32            // pairs per CTA
#define MROWS   128           // 4 domains * NP
#define KC      16            // K per chunk (one k16 MMA step)
#define NCH     (CH/KC)       // 24 chunks
#define APAD    24            // halves per smem row (16 + 8 pad) -> 48B stride, LDSM conflict-free
#define BROWS   (4*CH)        // 1536 weight rows (4 domains x 384 outputs)
#define NTHR    512

// smem layout (bytes)
#define A_BYTES (MROWS*APAD*2)        // 6144
#define B_BYTES (BROWS*APAD*2)        // 73728
#define STAGE_BYTES (A_BYTES+B_BYTES) // 79872 (x2 stages = 159744)
#define MSTRIDE 388                   // floats, padded
#define M_BYTES (MROWS*MSTRIDE*4)     // 198656 (overlays tile stages after mainloop)
#define OFF_PARAM M_BYTES             // 198656
#define SMEM_TOTAL (OFF_PARAM + 4*CH*4)  // 204800

// ---------------- device scratch (no allocations allowed) ----------------
__device__ __nv_bfloat16 g_t [4*NPAIRS*CH];   // transformed inputs [d][pair][c] (reused layer1->layer2)
__device__ __nv_bfloat16 g_h1[ROWS*CH];       // layer-1 output (bf16)
__device__ __nv_bfloat16 g_u1[4*CH*CH];       // transformed weights layer1 [d][o][c]
__device__ __nv_bfloat16 g_u2[4*CH*CH];
__device__ int           g_cum[ROWS];         // per-batch cumsum of durations

// ---------------- prep kernels ----------------
// weight transform: w [3][C][O] fp32 -> U_d [d][o][c] bf16
__global__ void wtrans_kernel(const float* __restrict__ w, int which) {
    int idx = blockIdx.x * blockDim.x + threadIdx.x;   // o*384 + c
    if (idx >= CH * CH) return;
    int o = idx / CH, c = idx - o * CH;
    float w0 = w[              c * CH + o];
    float w1 = w[  CH * CH +   c * CH + o];
    float w2 = w[2 * CH * CH + c * CH + o];
    __nv_bfloat16* G = which ? g_u2 : g_u1;
    G[0 * CH * CH + idx] = __float2bfloat16(w0);
    G[1 * CH * CH + idx] = __float2bfloat16((w0 + w1 + w2) * 0.5f);
    G[2 * CH * CH + idx] = __float2bfloat16((w0 - w1 + w2) * 0.5f);
    G[3 * CH * CH + idx] = __float2bfloat16(w2);
}

// input transform from fp32 x (layer 1): d_i = rows 2p-1..2p+2 (zero pad at batch edges)
__global__ void itrans_x_kernel(const float* __restrict__ x) {
    int idx = blockIdx.x * blockDim.x + threadIdx.x;   // q*192 + c2
    if (idx >= NPAIRS * (CH / 2)) return;
    int q = idx / (CH / 2), c2 = idx - q * (CH / 2);
    int b = q >> 9, lp = q & (PPB - 1);
    const float* xb = x + (size_t)b * SEQ * CH + c2 * 2;
    float2 z = make_float2(0.f, 0.f);
    float2 d0 = (lp > 0)       ? *(const float2*)(xb + (size_t)(2 * lp - 1) * CH) : z;
    float2 d1 =                  *(const float2*)(xb + (size_t)(2 * lp    ) * CH);
    float2 d2 =                  *(const float2*)(xb + (size_t)(2 * lp + 1) * CH);
    float2 d3 = (lp < PPB - 1) ? *(const float2*)(xb + (size_t)(2 * lp + 2) * CH) : z;
    size_t o = (size_t)q * CH + c2 * 2;
    ((__nv_bfloat162*)(g_t + 0 * (size_t)NPAIRS * CH + o))[0] = __floats2bfloat162_rn(d0.x - d2.x, d0.y - d2.y);
    ((__nv_bfloat162*)(g_t + 1 * (size_t)NPAIRS * CH + o))[0] = __floats2bfloat162_rn(d1.x + d2.x, d1.y + d2.y);
    ((__nv_bfloat162*)(g_t + 2 * (size_t)NPAIRS * CH + o))[0] = __floats2bfloat162_rn(d2.x - d1.x, d2.y - d1.y);
    ((__nv_bfloat162*)(g_t + 3 * (size_t)NPAIRS * CH + o))[0] = __floats2bfloat162_rn(d1.x - d3.x, d1.y - d3.y);
}

// input transform from bf16 h1 (layer 2)
__global__ void itrans_h_kernel() {
    int idx = blockIdx.x * blockDim.x + threadIdx.x;
    if (idx >= NPAIRS * (CH / 2)) return;
    int q = idx / (CH / 2), c2 = idx - q * (CH / 2);
    int b = q >> 9, lp = q & (PPB - 1);
    const __nv_bfloat16* hb = g_h1 + (size_t)b * SEQ * CH + c2 * 2;
    float2 z = make_float2(0.f, 0.f);
    float2 d0 = z, d3 = z;
    if (lp > 0)       { __nv_bfloat162 v = *(const __nv_bfloat162*)(hb + (size_t)(2 * lp - 1) * CH); d0 = __bfloat1622float2(v); }
    { __nv_bfloat162 v = *(const __nv_bfloat162*)(hb + (size_t)(2 * lp    ) * CH); float2 t = __bfloat1622float2(v);
      __nv_bfloat162 u = *(const __nv_bfloat162*)(hb + (size_t)(2 * lp + 1) * CH); float2 s = __bfloat1622float2(u);
      if (lp < PPB - 1) { __nv_bfloat162 w = *(const __nv_bfloat162*)(hb + (size_t)(2 * lp + 2) * CH); d3 = __bfloat1622float2(w); }
      size_t o = (size_t)q * CH + c2 * 2;
      ((__nv_bfloat162*)(g_t + 0 * (size_t)NPAIRS * CH + o))[0] = __floats2bfloat162_rn(d0.x - s.x, d0.y - s.y);
      ((__nv_bfloat162*)(g_t + 1 * (size_t)NPAIRS * CH + o))[0] = __floats2bfloat162_rn(t.x + s.x, t.y + s.y);
      ((__nv_bfloat162*)(g_t + 2 * (size_t)NPAIRS * CH + o))[0] = __floats2bfloat162_rn(s.x - t.x, s.y - t.y);
      ((__nv_bfloat162*)(g_t + 3 * (size_t)NPAIRS * CH + o))[0] = __floats2bfloat162_rn(t.x - d3.x, t.y - d3.y);
    }
}

__global__ void cumsum_kernel(const int* __restrict__ dur) {
    __shared__ int s[SEQ];
    int b = blockIdx.x, t = threadIdx.x;
    s[t] = dur[b * SEQ + t];
    __syncthreads();
    #pragma unroll
    for (int off = 1; off < SEQ; off <<= 1) {
        int v = (t >= off) ? s[t - off] : 0;
        __syncthreads();
        s[t] += v;
        __syncthreads();
    }
    g_cum[b * SEQ + t] = s[t];
}

// ---------------- ptx helpers ----------------
__device__ __forceinline__ void mma16816(float* c, const uint32_t* a, uint32_t b0, uint32_t b1) {
    asm volatile(
        "mma.sync.aligned.m16n8k16.row.col.f32.bf16.bf16.f32 "
        "{%0,%1,%2,%3}, {%4,%5,%6,%7}, {%8,%9}, {%0,%1,%2,%3};\n"
        : "+f"(c[0]), "+f"(c[1]), "+f"(c[2]), "+f"(c[3])
        : "r"(a[0]), "r"(a[1]), "r"(a[2]), "r"(a[3]), "r"(b0), "r"(b1));
}
__device__ __forceinline__ void ldsm4(uint32_t* r, uint32_t addr) {
    asm volatile("ldmatrix.sync.aligned.m8n8.x4.shared.b16 {%0,%1,%2,%3}, [%4];\n"
                 : "=r"(r[0]), "=r"(r[1]), "=r"(r[2]), "=r"(r[3]) : "r"(addr));
}
__device__ __forceinline__ void cp_async16(uint32_t dst, const void* gptr) {
    asm volatile("cp.async.cg.shared.global [%0], [%1], 16;\n" :: "r"(dst), "l"(gptr));
}
__device__ __forceinline__ void cp_commit() { asm volatile("cp.async.commit_group;\n"); }
__device__ __forceinline__ void cp_wait1()  { asm volatile("cp.async.wait_group 1;\n"); }
__device__ __forceinline__ void cp_wait0()  { asm volatile("cp.async.wait_group 0;\n"); }

// ---------------- Winograd conv + bias + LN + ReLU [-> h1 | -> @wl+bl -> exp] ----------------
// Per CTA: m[d][p][o] = t_d[P0+p] . U_d^T  for d=0..3, p=0..31, o=0..383 (K=384)
// Then y_even = m0+m1+m2, y_odd = m1-m2-m3, + bias, LN, ReLU, store / predict.
template<bool PRED>
__global__ __launch_bounds__(NTHR, 1)
void convw_kernel(const float* __restrict__ bias,
                  const float* __restrict__ gamma,
                  const float* __restrict__ beta,
                  const float* __restrict__ wl,
                  const float* __restrict__ bl,
                  float* __restrict__ pred)
{
    extern __shared__ char smem[];
    const uint32_t sb = (uint32_t)__cvta_generic_to_shared(smem);
    float* sBias  = (float*)(smem + OFF_PARAM);
    float* sGamma = sBias  + CH;
    float* sBeta  = sGamma + CH;
    float* sWl    = sBeta  + CH;
    float* M      = (float*)smem;   // [128][MSTRIDE] fp32, valid after mainloop

    const __nv_bfloat16* U = PRED ? g_u2 : g_u1;

    const int tid = threadIdx.x;
    const int P0  = blockIdx.x * NP;          // pair base (never straddles a batch: 16 CTAs/batch)

    if (tid < CH) {
        sBias[tid]  = bias[tid];
        sGamma[tid] = gamma[tid];
        sBeta[tid]  = beta[tid];
        sWl[tid]    = PRED ? wl[tid] : 0.0f;
    }

    // ---- chunk loader ----
    auto load_chunk = [&](int ci, int st) {
        const int c0 = ci * KC;
        const uint32_t Ad = sb + st * STAGE_BYTES;
        const uint32_t Bd = Ad + A_BYTES;
        if (tid < 256) {                       // A: 128 rows x 32B = 256 x 16B
            int row = tid >> 1, seg = tid & 1; // row = d*32 + p
            int d = row >> 5, p = row & 31;
            cp_async16(Ad + (row * APAD + seg * 8) * 2,
                       g_t + ((size_t)d * NPAIRS + P0 + p) * CH + c0 + seg * 8);
        }
        #pragma unroll
        for (int e = 0; e < 6; e++) {          // B: 1536 rows x 32B = 3072 x 16B
            int j = e * NTHR + tid;
            int row = j >> 1, seg = j & 1;     // row = d*384 + o
            cp_async16(Bd + (row * APAD + seg * 8) * 2,
                       U + (size_t)row * CH + c0 + seg * 8);
        }
    };

    const int wid = tid >> 5, lane = tid & 31;
    const int wm = wid >> 2, wn = wid & 3;     // wm = domain d, wn = 96-col group

    const int aRow = wm * 32 + (lane & 7) + ((lane >> 3) & 1) * 8;
    const uint32_t aBase = (uint32_t)((aRow * APAD + (lane >> 4) * 8) * 2);
    const int bRow = wm * CH + wn * 96 + (lane & 7) + ((lane >> 4) & 1) * 8;
    const uint32_t bBase = (uint32_t)((bRow * APAD + ((lane >> 3) & 1) * 8) * 2);

    float c[2][12][4];
    #pragma unroll
    for (int mt = 0; mt < 2; mt++)
        #pragma unroll
        for (int nt = 0; nt < 12; nt++)
            #pragma unroll
            for (int i = 0; i < 4; i++) c[mt][nt][i] = 0.0f;

    load_chunk(0, 0); cp_commit();
    load_chunk(1, 1); cp_commit();

    for (int ci = 0; ci < NCH; ci++) {
        const int st = ci & 1;
        if (ci < NCH - 1) cp_wait1(); else cp_wait0();
        __syncthreads();

        const uint32_t As = sb + st * STAGE_BYTES + aBase;
        const uint32_t Bs = sb + st * STAGE_BYTES + A_BYTES + bBase;
        uint32_t a[2][4];
        ldsm4(a[0], As);
        ldsm4(a[1], As + 16 * APAD * 2);
        #pragma unroll
        for (int np = 0; np < 6; np++) {
            uint32_t bb[4];
            ldsm4(bb, Bs + np * 16 * APAD * 2);
            mma16816(c[0][2*np  ], a[0], bb[0], bb[1]);
            mma16816(c[1][2*np  ], a[1], bb[0], bb[1]);
            mma16816(c[0][2*np+1], a[0], bb[2], bb[3]);
            mma16816(c[1][2*np+1], a[1], bb[2], bb[3]);
        }
        __syncthreads();                       // all reads of stage st done
        if (ci + 2 < NCH) { load_chunk(ci + 2, st); cp_commit(); }
    }
    __syncthreads();                           // mainloop fully done before M overlay

    // ---- spill m to smem ----
    const int g = lane >> 2, tg = lane & 3;
    #pragma unroll
    for (int mt = 0; mt < 2; mt++)
        #pragma unroll
        for (int nt = 0; nt < 12; nt++) {
            int row = wm * 32 + mt * 16 + g;
            int col = wn * 96 + nt * 8 + tg * 2;
            M[row * MSTRIDE + col]           = c[mt][nt][0];
            M[row * MSTRIDE + col + 1]       = c[mt][nt][1];
            M[(row + 8) * MSTRIDE + col]     = c[mt][nt][2];
            M[(row + 8) * MSTRIDE + col + 1] = c[mt][nt][3];
        }
    __syncthreads();

    // ---- combine + bias + LN + ReLU (+ store / predict) ----
    // 64 output rows per CTA; 8 threads per row, 48 cols each.
    const int orow = tid >> 3;                 // 0..63
    const int p    = orow >> 1;
    const int odd  = orow & 1;
    const int j0   = (tid & 7) * 48;

    const float* m0 = M + (0 * NP + p) * MSTRIDE + j0;
    const float* m1 = M + (1 * NP + p) * MSTRIDE + j0;
    const float* m2 = M + (2 * NP + p) * MSTRIDE + j0;
    const float* m3 = M + (3 * NP + p) * MSTRIDE + j0;

    float y[48];
    float sum = 0.f, sq = 0.f;
    if (!odd) {
        #pragma unroll
        for (int i = 0; i < 12; i++) {
            float4 A0 = *(const float4*)(m0 + i * 4);
            float4 A1 = *(const float4*)(m1 + i * 4);
            float4 A2 = *(const float4*)(m2 + i * 4);
            y[i*4+0] = A0.x + A1.x + A2.x;
            y[i*4+1] = A0.y + A1.y + A2.y;
            y[i*4+2] = A0.z + A1.z + A2.z;
            y[i*4+3] = A0.w + A1.w + A2.w;
        }
    } else {
        #pragma unroll
        for (int i = 0; i < 12; i++) {
            float4 A1 = *(const float4*)(m1 + i * 4);
            float4 A2 = *(const float4*)(m2 + i * 4);
            float4 A3 = *(const float4*)(m3 + i * 4);
            y[i*4+0] = A1.x - A2.x - A3.x;
            y[i*4+1] = A1.y - A2.y - A3.y;
            y[i*4+2] = A1.z - A2.z - A3.z;
            y[i*4+3] = A1.w - A2.w - A3.w;
        }
    }
    #pragma unroll
    for (int i = 0; i < 48; i++) {
        y[i] += sBias[j0 + i];
        sum += y[i];
        sq  += y[i] * y[i];
    }
    // 8-thread reduce (lanes tid&7 within same warp)
    #pragma unroll
    for (int m = 1; m < 8; m <<= 1) {
        sum += __shfl_xor_sync(0xffffffffu, sum, m);
        sq  += __shfl_xor_sync(0xffffffffu, sq,  m);
    }
    const float mean = sum * (1.0f / CH);
    const float rstd = rsqrtf(sq * (1.0f / CH) - mean * mean + 1e-5f);

    const int q = P0 + p;
    const int b = q >> 9;
    const int s = ((q & (PPB - 1)) << 1) | odd;
    const size_t grow = ((size_t)b * SEQ + s) * CH;

    if (!PRED) {
        uint32_t pk[24];
        #pragma unroll
        for (int i = 0; i < 24; i++) {
            float v0 = fmaxf(0.f, (y[2*i]   - mean) * rstd * sGamma[j0 + 2*i]   + sBeta[j0 + 2*i]);
            float v1 = fmaxf(0.f, (y[2*i+1] - mean) * rstd * sGamma[j0 + 2*i+1] + sBeta[j0 + 2*i+1]);
            __nv_bfloat162 p2 = __floats2bfloat162_rn(v0, v1);
            pk[i] = *(uint32_t*)&p2;
        }
        uint4* dst = (uint4*)(g_h1 + grow + j0);
        #pragma unroll
        for (int i = 0; i < 6; i++)
            dst[i] = make_uint4(pk[4*i], pk[4*i+1], pk[4*i+2], pk[4*i+3]);
    } else {
        float pd = 0.f;
        #pragma unroll
        for (int i = 0; i < 48; i++) {
            float v = fmaxf(0.f, (y[i] - mean) * rstd * sGamma[j0 + i] + sBeta[j0 + i]);
            pd += v * sWl[j0 + i];
        }
        #pragma unroll
        for (int m = 1; m < 8; m <<= 1)
            pd += __shfl_xor_sync(0xffffffffu, pd, m);
        if ((tid & 7) == 0)
            pred[(size_t)b * SEQ + s] = expf(pd + bl[0]);
    }
}

// ---------------- length regulation (exact gather of fp32 x) ----------------
__global__ void gather_kernel(const float* __restrict__ x, float* __restrict__ out) {
    __shared__ int sc[SEQ];
    int b = blockIdx.y;
    for (int i = threadIdx.x; i < SEQ; i += blockDim.x) sc[i] = g_cum[b * SEQ + i];
    __syncthreads();

    int warp = threadIdx.x >> 5, lane = threadIdx.x & 31;
    int t = blockIdx.x * 8 + warp;            // 0..3071
    int total = sc[SEQ - 1];
    bool valid = t < total;
    int lo = 0, hi = SEQ;
    while (lo < hi) { int mid = (lo + hi) >> 1; if (sc[mid] <= t) lo = mid + 1; else hi = mid; }
    int src = min(lo, SEQ - 1);

    const float4* xp = (const float4*)(x + ((size_t)b * SEQ + src) * CH);
    float4* op = (float4*)(out + ((size_t)b * MAXOUT + t) * CH);
    #pragma unroll
    for (int i = 0; i < 3; i++) {
        float4 v = valid ? xp[lane + 32 * i] : make_float4(0.f, 0.f, 0.f, 0.f);
        op[lane + 32 * i] = v;
    }
}

// ---------------- launch ----------------
extern "C" void kernel_launch(void* const* d_in, const int* in_sizes, int n_in,
                              void* d_out, int out_size) {
    const float* x     = (const float*)d_in[0];
    const int*   dur   = (const int*)  d_in[1];
    const float* w1    = (const float*)d_in[2];
    const float* b1    = (const float*)d_in[3];
    const float* g1    = (const float*)d_in[4];
    const float* beta1 = (const float*)d_in[5];
    const float* w2    = (const float*)d_in[6];
    const float* b2    = (const float*)d_in[7];
    const float* g2    = (const float*)d_in[8];
    const float* beta2 = (const float*)d_in[9];
    const float* wl    = (const float*)d_in[10];
    const float* bl    = (const float*)d_in[11];

    float* res  = (float*)d_out;
    float* pred = res + (size_t)BATCH * MAXOUT * CH;

    static cudaStream_t s_aux = nullptr;
    static cudaEvent_t  ev_fork = nullptr, ev_join = nullptr;
    static bool s_init = false;
    if (!s_init) {
        cudaStreamCreateWithFlags(&s_aux, cudaStreamNonBlocking);
        cudaEventCreateWithFlags(&ev_fork, cudaEventDisableTiming);
        cudaEventCreateWithFlags(&ev_join, cudaEventDisableTiming);
        cudaFuncSetAttribute(convw_kernel<false>, cudaFuncAttributeMaxDynamicSharedMemorySize, SMEM_TOTAL);
        cudaFuncSetAttribute(convw_kernel<true>,  cudaFuncAttributeMaxDynamicSharedMemorySize, SMEM_TOTAL);
        s_init = true;
    }

    // ---- fork: aux branch = cumsum -> gather (memory-bound, independent of convs) ----
    cudaEventRecord(ev_fork, 0);
    cudaStreamWaitEvent(s_aux, ev_fork, 0);
    cumsum_kernel<<<BATCH, SEQ, 0, s_aux>>>(dur);
    gather_kernel<<<dim3(MAXOUT / 8, BATCH), 256, 0, s_aux>>>(x, res);
    cudaEventRecord(ev_join, s_aux);

    // ---- main branch: transforms + Winograd convs ----
    wtrans_kernel<<<(CH * CH + 255) / 256, 256>>>(w1, 0);
    wtrans_kernel<<<(CH * CH + 255) / 256, 256>>>(w2, 1);

    int nel = NPAIRS * (CH / 2);
    itrans_x_kernel<<<(nel + 255) / 256, 256>>>(x);
    convw_kernel<false><<<NPAIRS / NP, NTHR, SMEM_TOTAL>>>(b1, g1, beta1, nullptr, nullptr, nullptr);
    itrans_h_kernel<<<(nel + 255) / 256, 256>>>();
    convw_kernel<true><<<NPAIRS / NP, NTHR, SMEM_TOTAL>>>(b2, g2, beta2, wl, bl, pred);

    // ---- join ----
    cudaStreamWaitEvent(0, ev_join, 0);
}

// round 9
// speedup vs baseline: 2.0073x; 2.0073x over previous
#include <cuda_runtime.h>
#include <cuda_bf16.h>
#include <cstdint>
#include <math.h>

// ---------------- problem constants ----------------
#define BATCH   32
#define SEQ     1024
#define CH      384          // C == H == 384
#define KTOT    1152         // 3 * 384
#define MAXOUT  3072
#define ROWS    (BATCH*SEQ)  // 32768

// GEMM tiling
#define TM      128
#define KC      32
#define NITER   (KTOT/KC)    // 36
#define APAD    40           // halves per A smem row (32 + 8 pad) -> 80B stride, LDSM conflict-free
#define BPAD    40
#define NTHR    512
#define NSTAGE  4
#define NTILES  256          // conv tiles per layer

// smem layout (bytes)
#define A_BYTES (TM*APAD*2)                    // 10240
#define B_BYTES (CH*BPAD*2)                    // 30720
#define OFF_B     (NSTAGE*A_BYTES)             // 40960
#define OFF_PARAM (OFF_B + NSTAGE*B_BYTES)     // 163840
#define OFF_PART  (OFF_PARAM + 4*CH*4)         // 169984
#define OFF_MEAN  (OFF_PART + TM*8*4)          // 174080
#define OFF_RSTD  (OFF_MEAN + TM*4)            // 174592
#define SMEM_TOTAL (OFF_RSTD + TM*4)           // 175104

// ---------------- device scratch (no allocations allowed) ----------------
__device__ __nv_bfloat16 g_xbf[ROWS*CH];     // bf16 copy of x
__device__ __nv_bfloat16 g_h1 [ROWS*CH];     // layer-1 output (bf16)
__device__ __nv_bfloat16 g_w1T[CH*KTOT];     // w1 transposed: [o][k*CH+c]
__device__ __nv_bfloat16 g_w2T[CH*KTOT];
__device__ int           g_cum[ROWS];        // per-batch cumsum of durations
__device__ int           g_flag[NTILES];     // layer-1 tile completion flags

// ---------------- merged prep kernel: cvt_x + cvt_w1 + cvt_w2 + flag reset ----------------
#define N2     (ROWS*CH/2)                    // 6291456 float2->bf162 conversions
#define WN     (CH*KTOT)                      // 442368 per weight
#define PREP_TOTAL (N2 + 2*WN + NTILES)

__global__ void prep_kernel(const float* __restrict__ x,
                            const float* __restrict__ w1,
                            const float* __restrict__ w2) {
    int i = blockIdx.x * blockDim.x + threadIdx.x;
    if (i < N2) {
        float2 v = reinterpret_cast<const float2*>(x)[i];
        reinterpret_cast<__nv_bfloat162*>(g_xbf)[i] = __floats2bfloat162_rn(v.x, v.y);
    } else if (i < N2 + 2*WN) {
        int j = i - N2;
        const float* w = (j < WN) ? w1 : w2;
        __nv_bfloat16* dst = (j < WN) ? g_w1T : g_w2T;
        if (j >= WN) j -= WN;
        int o  = j / KTOT;
        int kc = j - o * KTOT;
        dst[j + o * 0] = __float2bfloat16(w[(size_t)kc * CH + o]);
        dst[(size_t)o * KTOT + kc] = __float2bfloat16(w[(size_t)kc * CH + o]);
    } else if (i < PREP_TOTAL) {
        g_flag[i - N2 - 2*WN] = 0;
    }
}

__global__ void cumsum_kernel(const int* __restrict__ dur) {
    __shared__ int s[SEQ];
    int b = blockIdx.x, t = threadIdx.x;
    s[t] = dur[b * SEQ + t];
    __syncthreads();
    #pragma unroll
    for (int off = 1; off < SEQ; off <<= 1) {
        int v = (t >= off) ? s[t - off] : 0;
        __syncthreads();
        s[t] += v;
        __syncthreads();
    }
    g_cum[b * SEQ + t] = s[t];
}

// ---------------- ptx helpers ----------------
__device__ __forceinline__ void mma16816(float* c, const uint32_t* a, uint32_t b0, uint32_t b1) {
    asm volatile(
        "mma.sync.aligned.m16n8k16.row.col.f32.bf16.bf16.f32 "
        "{%0,%1,%2,%3}, {%4,%5,%6,%7}, {%8,%9}, {%0,%1,%2,%3};\n"
        : "+f"(c[0]), "+f"(c[1]), "+f"(c[2]), "+f"(c[3])
        : "r"(a[0]), "r"(a[1]), "r"(a[2]), "r"(a[3]), "r"(b0), "r"(b1));
}
__device__ __forceinline__ void ldsm4(uint32_t* r, uint32_t addr) {
    asm volatile("ldmatrix.sync.aligned.m8n8.x4.shared.b16 {%0,%1,%2,%3}, [%4];\n"
                 : "=r"(r[0]), "=r"(r[1]), "=r"(r[2]), "=r"(r[3]) : "r"(addr));
}
__device__ __forceinline__ void cp_async16(uint32_t dst, const void* gptr, int sz) {
    asm volatile("cp.async.cg.shared.global [%0], [%1], 16, %2;\n" :: "r"(dst), "l"(gptr), "r"(sz));
}
__device__ __forceinline__ void cp_async16(uint32_t dst, const void* gptr) {
    asm volatile("cp.async.cg.shared.global [%0], [%1], 16;\n" :: "r"(dst), "l"(gptr));
}
__device__ __forceinline__ void cp_commit() { asm volatile("cp.async.commit_group;\n"); }
__device__ __forceinline__ void cp_wait2()  { asm volatile("cp.async.wait_group 2;\n"); }
__device__ __forceinline__ void cp_wait1()  { asm volatile("cp.async.wait_group 1;\n"); }
__device__ __forceinline__ void cp_wait0()  { asm volatile("cp.async.wait_group 0;\n"); }

// ---------------- merged dual-layer conv kernel ----------------
// Blocks 0..255:   layer 1 tiles -> g_h1 + completion flag
// Blocks 256..511: layer 2 tiles (spin on the <=3 neighbor flags they read) -> pred
__global__ __launch_bounds__(NTHR, 1)
void conv_ln_kernel(const float* __restrict__ b1v,
                    const float* __restrict__ g1v,
                    const float* __restrict__ be1v,
                    const float* __restrict__ b2v,
                    const float* __restrict__ g2v,
                    const float* __restrict__ be2v,
                    const float* __restrict__ wl,
                    const float* __restrict__ bl,
                    float* __restrict__ pred)
{
    extern __shared__ char smem[];
    const uint32_t smem_base = (uint32_t)__cvta_generic_to_shared(smem);
    float* sBias  = (float*)(smem + OFF_PARAM);
    float* sGamma = sBias  + CH;
    float* sBeta  = sGamma + CH;
    float* sWl    = sBeta  + CH;
    float* sPart  = (float*)(smem + OFF_PART);   // [TM][8]
    float* sMean  = (float*)(smem + OFF_MEAN);   // [TM]
    float* sRstd  = (float*)(smem + OFF_RSTD);   // [TM]

    const bool PRED = blockIdx.x >= NTILES;
    const int  bidx = PRED ? (blockIdx.x - NTILES) : blockIdx.x;   // tile 0..255

    const __nv_bfloat16* Ain = PRED ? g_h1  : g_xbf;
    const __nv_bfloat16* WT  = PRED ? g_w2T : g_w1T;
    const float* bias  = PRED ? b2v  : b1v;
    const float* gamma = PRED ? g2v  : g1v;
    const float* beta  = PRED ? be2v : be1v;

    const int tid  = threadIdx.x;
    const int b    = bidx >> 3;             // 8 tiles per batch (1024/128)
    const int s0   = (bidx & 7) * TM;
    const size_t rowBase = (size_t)b * SEQ;

    if (tid < CH) {
        sBias[tid]  = bias[tid];
        sGamma[tid] = gamma[tid];
        sBeta[tid]  = beta[tid];
        sWl[tid]    = PRED ? wl[tid] : 0.0f;
    }

    // ---- layer-2 blocks: wait for the layer-1 tiles whose rows we read ----
    if (PRED) {
        if (tid == 0) {
            int i = bidx & 7, base = bidx & ~7;
            int lo = base + max(i - 1, 0), hi = base + min(i + 1, 7);
            for (int d = lo; d <= hi; d++)
                while (*(volatile int*)&g_flag[d] == 0) {}
        }
        __threadfence();
        __syncthreads();
    }

    // ---- tile loader (cp.async, padded layout) ----
    auto load_tile = [&](int ci, int st) {
        const int k  = ci / 12;             // conv tap 0..2
        const int c0 = (ci % 12) * KC;      // channel base within tap
        const uint32_t Ad = smem_base + st * A_BYTES;
        const uint32_t Bd = smem_base + OFF_B + st * B_BYTES;
        {   // A: 128 rows x 64B = 512 x 16B reqs, 1 per thread
            int r = tid >> 2, seg = tid & 3;
            int gs = s0 + r + k - 1;                // batch-local padded row
            bool ok = (unsigned)gs < (unsigned)SEQ;
            const void* src = ok ? (const void*)(Ain + (rowBase + gs) * CH + c0 + seg * 8)
                                 : (const void*)Ain;
            cp_async16(Ad + (r * APAD + seg * 8) * 2, src, ok ? 16 : 0);
        }
        // B: 384 rows x 64B = 1536 reqs, 3 per thread
        #pragma unroll
        for (int e = 0; e < 3; e++) {
            int j = tid + e * NTHR;
            int n = j >> 2, seg = j & 3;
            cp_async16(Bd + (n * BPAD + seg * 8) * 2,
                       WT + (size_t)n * KTOT + ci * KC + seg * 8);
        }
    };

    const int wid = tid >> 5, lane = tid & 31;
    const int wm = wid >> 2, wn = wid & 3;   // 4x4 warp grid; warp tile 32(M) x 96(N)

    const int aRow = wm * 32 + (lane & 7) + ((lane >> 3) & 1) * 8;
    const int aCol = (lane >> 4) * 8;                    // halves
    const uint32_t aBase = (uint32_t)((aRow * APAD + aCol) * 2);
    const int bRow = wn * 96 + (lane & 7) + ((lane >> 4) & 1) * 8;
    const int bCol = ((lane >> 3) & 1) * 8;              // halves
    const uint32_t bBase = (uint32_t)((bRow * BPAD + bCol) * 2);

    float c[2][12][4];
    #pragma unroll
    for (int mt = 0; mt < 2; mt++)
        #pragma unroll
        for (int nt = 0; nt < 12; nt++)
            #pragma unroll
            for (int i = 0; i < 4; i++) c[mt][nt][i] = 0.0f;

    load_tile(0, 0); cp_commit();
    load_tile(1, 1); cp_commit();

    for (int ci = 0; ci < NITER; ci++) {
        const int st = ci & 3;
        if (ci + 2 < NITER) { load_tile(ci + 2, (ci + 2) & 3); cp_commit(); cp_wait2(); }
        else if (ci == NITER - 2) cp_wait1();
        else cp_wait0();
        __syncthreads();

        const uint32_t Asb = smem_base + st * A_BYTES + aBase;
        const uint32_t Bsb = smem_base + OFF_B + st * B_BYTES + bBase;
        #pragma unroll
        for (int ks = 0; ks < 2; ks++) {
            uint32_t a[2][4];
            ldsm4(a[0], Asb + ks * 32);                       // rows wm*32 +  0..15
            ldsm4(a[1], Asb + 16 * APAD * 2 + ks * 32);       // rows wm*32 + 16..31
            #pragma unroll
            for (int np = 0; np < 6; np++) {
                uint32_t bb[4];                               // 2 n8 fragments
                ldsm4(bb, Bsb + np * 16 * BPAD * 2 + ks * 32);
                mma16816(c[0][2*np  ], a[0], bb[0], bb[1]);
                mma16816(c[1][2*np  ], a[1], bb[0], bb[1]);
                mma16816(c[0][2*np+1], a[0], bb[2], bb[3]);
                mma16816(c[1][2*np+1], a[1], bb[2], bb[3]);
            }
        }
    }
    __syncthreads();

    // ---- epilogue: +bias, LayerNorm stats ----
    const int g = lane >> 2, tg = lane & 3;
    float psum[2][2] = {{0,0},{0,0}}, psq[2][2] = {{0,0},{0,0}};
    #pragma unroll
    for (int mt = 0; mt < 2; mt++)
        #pragma unroll
        for (int nt = 0; nt < 12; nt++) {
            int col0 = wn * 96 + nt * 8 + tg * 2;
            float bb0 = sBias[col0], bb1 = sBias[col0 + 1];
            c[mt][nt][0] += bb0; c[mt][nt][1] += bb1;
            c[mt][nt][2] += bb0; c[mt][nt][3] += bb1;
            psum[mt][0] += c[mt][nt][0] + c[mt][nt][1];
            psq [mt][0] += c[mt][nt][0]*c[mt][nt][0] + c[mt][nt][1]*c[mt][nt][1];
            psum[mt][1] += c[mt][nt][2] + c[mt][nt][3];
            psq [mt][1] += c[mt][nt][2]*c[mt][nt][2] + c[mt][nt][3]*c[mt][nt][3];
        }
    #pragma unroll
    for (int mt = 0; mt < 2; mt++)
        #pragma unroll
        for (int hi = 0; hi < 2; hi++) {
            float s = psum[mt][hi], q = psq[mt][hi];
            s += __shfl_xor_sync(0xffffffffu, s, 1); s += __shfl_xor_sync(0xffffffffu, s, 2);
            q += __shfl_xor_sync(0xffffffffu, q, 1); q += __shfl_xor_sync(0xffffffffu, q, 2);
            if (tg == 0) {
                int r = wm * 32 + mt * 16 + g + 8 * hi;
                sPart[r * 8 + wn] = s;
                sPart[r * 8 + 4 + wn] = q;
            }
        }
    __syncthreads();
    if (tid < TM) {
        float s = sPart[tid*8+0] + sPart[tid*8+1] + sPart[tid*8+2] + sPart[tid*8+3];
        float q = sPart[tid*8+4] + sPart[tid*8+5] + sPart[tid*8+6] + sPart[tid*8+7];
        float mean = s * (1.0f / CH);
        float var  = q * (1.0f / CH) - mean * mean;
        sMean[tid] = mean;
        sRstd[tid] = rsqrtf(var + 1e-5f);
    }
    __syncthreads();

    // ---- normalize + relu; store bf16 OR fused linear+exp ----
    float pd[2][2] = {{0,0},{0,0}};
    #pragma unroll
    for (int mt = 0; mt < 2; mt++) {
        int r0 = wm * 32 + mt * 16 + g;
        float m0 = sMean[r0],   rs0 = sRstd[r0];
        float m1 = sMean[r0+8], rs1 = sRstd[r0+8];
        #pragma unroll
        for (int nt = 0; nt < 12; nt++) {
            int col0 = wn * 96 + nt * 8 + tg * 2;
            float ga0 = sGamma[col0], ga1 = sGamma[col0+1];
            float be0 = sBeta[col0],  be1 = sBeta[col0+1];
            float v0 = fmaxf(0.f, (c[mt][nt][0] - m0) * rs0 * ga0 + be0);
            float v1 = fmaxf(0.f, (c[mt][nt][1] - m0) * rs0 * ga1 + be1);
            float v2 = fmaxf(0.f, (c[mt][nt][2] - m1) * rs1 * ga0 + be0);
            float v3 = fmaxf(0.f, (c[mt][nt][3] - m1) * rs1 * ga1 + be1);
            if (!PRED) {
                size_t base0 = (rowBase + s0 + r0) * CH + col0;
                *(__nv_bfloat162*)(g_h1 + base0)          = __floats2bfloat162_rn(v0, v1);
                *(__nv_bfloat162*)(g_h1 + base0 + 8 * CH) = __floats2bfloat162_rn(v2, v3);
            } else {
                float w0 = sWl[col0], w1v = sWl[col0 + 1];
                pd[mt][0] += v0 * w0 + v1 * w1v;
                pd[mt][1] += v2 * w0 + v3 * w1v;
            }
        }
    }
    if (!PRED) {
        // publish h1 tile: order stores before flag (release)
        __syncthreads();
        __threadfence();
        if (tid == 0) *(volatile int*)&g_flag[bidx] = 1;
    } else {
        #pragma unroll
        for (int mt = 0; mt < 2; mt++)
            #pragma unroll
            for (int hi = 0; hi < 2; hi++) {
                float s = pd[mt][hi];
                s += __shfl_xor_sync(0xffffffffu, s, 1);
                s += __shfl_xor_sync(0xffffffffu, s, 2);
                if (tg == 0) {
                    int r = wm * 32 + mt * 16 + g + 8 * hi;
                    sPart[r * 8 + wn] = s;
                }
            }
        __syncthreads();
        if (tid < TM) {
            float s = sPart[tid*8+0] + sPart[tid*8+1] + sPart[tid*8+2] + sPart[tid*8+3];
            pred[rowBase + s0 + tid] = expf(s + bl[0]);
        }
    }
}

// ---------------- length regulation (exact gather of fp32 x) ----------------
__global__ void gather_kernel(const float* __restrict__ x, float* __restrict__ out) {
    __shared__ int sc[SEQ];
    int b = blockIdx.y;
    for (int i = threadIdx.x; i < SEQ; i += blockDim.x) sc[i] = g_cum[b * SEQ + i];
    __syncthreads();

    int warp = threadIdx.x >> 5, lane = threadIdx.x & 31;
    int t = blockIdx.x * 8 + warp;            // 0..3071
    int total = sc[SEQ - 1];
    bool valid = t < total;
    int lo = 0, hi = SEQ;
    while (lo < hi) { int mid = (lo + hi) >> 1; if (sc[mid] <= t) lo = mid + 1; else hi = mid; }
    int src = min(lo, SEQ - 1);

    const float4* xp = (const float4*)(x + ((size_t)b * SEQ + src) * CH);
    float4* op = (float4*)(out + ((size_t)b * MAXOUT + t) * CH);
    #pragma unroll
    for (int i = 0; i < 3; i++) {
        float4 v = valid ? xp[lane + 32 * i] : make_float4(0.f, 0.f, 0.f, 0.f);
        op[lane + 32 * i] = v;
    }
}

// ---------------- launch ----------------
extern "C" void kernel_launch(void* const* d_in, const int* in_sizes, int n_in,
                              void* d_out, int out_size) {
    const float* x     = (const float*)d_in[0];
    const int*   dur   = (const int*)  d_in[1];
    const float* w1    = (const float*)d_in[2];
    const float* b1    = (const float*)d_in[3];
    const float* g1    = (const float*)d_in[4];
    const float* beta1 = (const float*)d_in[5];
    const float* w2    = (const float*)d_in[6];
    const float* b2    = (const float*)d_in[7];
    const float* g2    = (const float*)d_in[8];
    const float* beta2 = (const float*)d_in[9];
    const float* wl    = (const float*)d_in[10];
    const float* bl    = (const float*)d_in[11];

    float* res  = (float*)d_out;
    float* pred = res + (size_t)BATCH * MAXOUT * CH;

    static cudaStream_t s_aux = nullptr;
    static cudaEvent_t  ev_fork = nullptr, ev_join = nullptr;
    static bool s_init = false;
    if (!s_init) {
        cudaStreamCreateWithFlags(&s_aux, cudaStreamNonBlocking);
        cudaEventCreateWithFlags(&ev_fork, cudaEventDisableTiming);
        cudaEventCreateWithFlags(&ev_join, cudaEventDisableTiming);
        cudaFuncSetAttribute(conv_ln_kernel, cudaFuncAttributeMaxDynamicSharedMemorySize, SMEM_TOTAL);
        s_init = true;
    }

    // ---- fork: aux branch = cumsum -> gather (memory-bound, independent of convs) ----
    cudaEventRecord(ev_fork, 0);
    cudaStreamWaitEvent(s_aux, ev_fork, 0);
    cumsum_kernel<<<BATCH, SEQ, 0, s_aux>>>(dur);
    gather_kernel<<<dim3(MAXOUT / 8, BATCH), 256, 0, s_aux>>>(x, res);
    cudaEventRecord(ev_join, s_aux);

    // ---- main branch: merged prep, then dual-layer pipelined conv ----
    prep_kernel<<<(PREP_TOTAL + 255) / 256, 256>>>(x, w1, w2);
    conv_ln_kernel<<<2 * NTILES, NTHR, SMEM_TOTAL>>>(b1, g1, beta1, b2, g2, beta2, wl, bl, pred);

    // ---- join ----
    cudaStreamWaitEvent(0, ev_join, 0);
}